// round 17
// baseline (speedup 1.0000x reference)
#include <cuda_runtime.h>
#include <math.h>

#define MM 4096
#define DD 2048
#define INV_SQRT_M 0.015625f   // 1/sqrt(4096) exact

// ---------------- device scratch ----------------
__device__ float g_qt[MM];
__device__ float g_k[MM];
__device__ float g_v[MM];
__device__ float g_it, g_ft, g_ot;
__device__ float g_hf;             // hscale * ft  (folded atomic coefficient)

__device__ __forceinline__ float dot4(float4 a, float4 b) {
    return a.x * b.x + a.y * b.y + a.z * b.z + a.w * b.w;
}

// ---------------- kernel 1: fused q/k/v matvecs + gates (measured ~20.0us) ----------------
// grid = MM+1 blocks x 256 threads; block b < MM computes row b of Wq/Wk/Wv,
// block MM computes the three gates. 6 front-batched streaming loads/thread.
__global__ __launch_bounds__(256) void mv_kernel(
    const float* __restrict__ x,
    const float* __restrict__ Wq, const float* __restrict__ bq,
    const float* __restrict__ Wk, const float* __restrict__ bk,
    const float* __restrict__ Wv, const float* __restrict__ bV,
    const float* __restrict__ Wi, const float* __restrict__ bi,
    const float* __restrict__ Wf, const float* __restrict__ bf,
    const float* __restrict__ Wo, const float* __restrict__ bo)
{
    const int b = blockIdx.x;
    const int t = threadIdx.x;

    const bool gate = (b == MM);
    const float *rA, *rB, *rC;
    if (!gate) {
        rA = Wq + (size_t)b * DD;
        rB = Wk + (size_t)b * DD;
        rC = Wv + (size_t)b * DD;
    } else {
        rA = Wi; rB = Wf; rC = Wo;
    }

    const float4* A4 = reinterpret_cast<const float4*>(rA);
    const float4* B4 = reinterpret_cast<const float4*>(rB);
    const float4* C4 = reinterpret_cast<const float4*>(rC);
    const float4* x4 = reinterpret_cast<const float4*>(x);

    // 6 independent streaming loads, front-batched (MLP=6)
    float4 a0 = __ldcs(&A4[t]);
    float4 a1 = __ldcs(&A4[t + 256]);
    float4 k0 = __ldcs(&B4[t]);
    float4 k1 = __ldcs(&B4[t + 256]);
    float4 v0 = __ldcs(&C4[t]);
    float4 v1 = __ldcs(&C4[t + 256]);
    float4 x0 = x4[t];
    float4 x1 = x4[t + 256];

    float sa = dot4(a0, x0) + dot4(a1, x1);
    float sk = dot4(k0, x0) + dot4(k1, x1);
    float sv = dot4(v0, x0) + dot4(v1, x1);

    #pragma unroll
    for (int o = 16; o > 0; o >>= 1) {
        sa += __shfl_down_sync(0xFFFFFFFFu, sa, o);
        sk += __shfl_down_sync(0xFFFFFFFFu, sk, o);
        sv += __shfl_down_sync(0xFFFFFFFFu, sv, o);
    }

    __shared__ float wsa[8], wsk[8], wsv[8];
    if ((t & 31) == 0) {
        const int w = t >> 5;
        wsa[w] = sa; wsk[w] = sk; wsv[w] = sv;
    }
    __syncthreads();
    if (t < 8) {
        float ra = wsa[t], rk = wsk[t], rv = wsv[t];
        #pragma unroll
        for (int o = 4; o > 0; o >>= 1) {
            ra += __shfl_down_sync(0xFFu, ra, o, 8);
            rk += __shfl_down_sync(0xFFu, rk, o, 8);
            rv += __shfl_down_sync(0xFFu, rv, o, 8);
        }
        if (t == 0) {
            if (!gate) {
                g_qt[b] = ra + bq[b];
                g_k[b]  = INV_SQRT_M * (rk + bk[b]);
                g_v[b]  = rv + bV[b];
            } else {
                g_it = expf(ra + bi[0]);
                g_ft = expf(rk + bf[0]);
                float z = rv + bo[0];
                g_ot = 1.0f / (1.0f + expf(-z));
            }
        }
    }
}

// ---------------- kernel 2: reductions + n-update + ht base init ----------------
// One block, 1024 threads.
// Phase A: kqt = k.qt ; npqt = n_prev.qt ; denom = max(|ft*npqt + it*kqt|,1)
//          (n.qt = ft*(n_prev.qt) + it*(k.qt), so n not needed first)
// Phase B: n_i = ft*n_prev_i + it*k_i  and  ht_i := hscale*it*v_i*kqt
//          (ht base term; cp_partial atomically adds hscale*ft*s_partials)
__global__ __launch_bounds__(1024) void nred2_kernel(
    const float* __restrict__ n_prev,
    float* __restrict__ out_n, float* __restrict__ outH)
{
    const int t = threadIdx.x;
    const float ft = g_ft, it = g_it;
    __shared__ float red[2][32];
    __shared__ float s_kqt, s_hscale;

    // ---- phase A ----
    float kqt = 0.f, npqt = 0.f;
    #pragma unroll
    for (int u = 0; u < MM / 1024; u++) {
        const int i = t + u * 1024;
        const float q = g_qt[i];
        kqt  += g_k[i] * q;
        npqt += n_prev[i] * q;
    }
    #pragma unroll
    for (int o = 16; o > 0; o >>= 1) {
        kqt  += __shfl_down_sync(0xFFFFFFFFu, kqt, o);
        npqt += __shfl_down_sync(0xFFFFFFFFu, npqt, o);
    }
    if ((t & 31) == 0) { red[0][t >> 5] = kqt; red[1][t >> 5] = npqt; }
    __syncthreads();
    if (t < 32) {
        float a = red[0][t], bb = red[1][t];
        #pragma unroll
        for (int o = 16; o > 0; o >>= 1) {
            a  += __shfl_down_sync(0xFFFFFFFFu, a, o);
            bb += __shfl_down_sync(0xFFFFFFFFu, bb, o);
        }
        if (t == 0) {
            const float nqt = ft * bb + it * a;
            const float hs  = g_ot / fmaxf(fabsf(nqt), 1.0f);
            s_kqt = a;
            s_hscale = hs;
            g_hf = hs * ft;
        }
    }
    __syncthreads();

    // ---- phase B: n-update + ht base ----
    const float kq = s_kqt;
    const float hs = s_hscale;
    #pragma unroll
    for (int u = 0; u < MM / 1024; u++) {
        const int i = t + u * 1024;
        const float k = g_k[i];
        const float np = n_prev[i];
        const float vv = g_v[i];
        out_n[i] = ft * np + it * k;
        outH[i]  = hs * (it * vv * kq);   // base; cp adds hs*ft*cp@qt
    }
}

// ---------------- kernel 3: sync-free cp stream + atomic ht fold ----------------
// One warp owns one 512-float chunk of one cp row: elementwise C write +
// warp-shuffle partial of cp@qt; lane 0 RED-adds hf*partial into ht[row].
// No smem, no syncthreads, no extra kernels. 4096 blocks x 256 threads.
__global__ __launch_bounds__(256) void cp_partial(
    const float* __restrict__ cp, float* __restrict__ outC,
    float* __restrict__ outH)
{
    const int w    = blockIdx.x * 8 + (threadIdx.x >> 5);
    const int lane = threadIdx.x & 31;
    const int row  = w >> 3;
    const int ch   = w & 7;

    const float ft = g_ft;
    const float iv = g_it * g_v[row];

    const size_t base = (size_t)row * MM + ch * 512;
    const float4* P  = reinterpret_cast<const float4*>(cp + base);
    float4*       O  = reinterpret_cast<float4*>(outC + base);
    const float4* k4 = reinterpret_cast<const float4*>(g_k + ch * 512);
    const float4* q4 = reinterpret_cast<const float4*>(g_qt + ch * 512);

    // 4 independent streaming loads front-batched
    float4 c0 = __ldcs(&P[lane]);
    float4 c1 = __ldcs(&P[lane + 32]);
    float4 c2 = __ldcs(&P[lane + 64]);
    float4 c3 = __ldcs(&P[lane + 96]);
    float4 k0 = k4[lane], k1 = k4[lane + 32], k2 = k4[lane + 64], k3 = k4[lane + 96];
    float4 q0 = q4[lane], q1 = q4[lane + 32], q2 = q4[lane + 64], q3 = q4[lane + 96];

    float4 o;
    o.x = ft * c0.x + iv * k0.x; o.y = ft * c0.y + iv * k0.y;
    o.z = ft * c0.z + iv * k0.z; o.w = ft * c0.w + iv * k0.w;
    __stcs(&O[lane], o);
    o.x = ft * c1.x + iv * k1.x; o.y = ft * c1.y + iv * k1.y;
    o.z = ft * c1.z + iv * k1.z; o.w = ft * c1.w + iv * k1.w;
    __stcs(&O[lane + 32], o);
    o.x = ft * c2.x + iv * k2.x; o.y = ft * c2.y + iv * k2.y;
    o.z = ft * c2.z + iv * k2.z; o.w = ft * c2.w + iv * k2.w;
    __stcs(&O[lane + 64], o);
    o.x = ft * c3.x + iv * k3.x; o.y = ft * c3.y + iv * k3.y;
    o.z = ft * c3.z + iv * k3.z; o.w = ft * c3.w + iv * k3.w;
    __stcs(&O[lane + 96], o);

    float s = dot4(c0, q0) + dot4(c1, q1) + dot4(c2, q2) + dot4(c3, q3);
    #pragma unroll
    for (int o2 = 16; o2 > 0; o2 >>= 1) s += __shfl_down_sync(0xFFFFFFFFu, s, o2);
    if (lane == 0) {
        atomicAdd(&outH[row], g_hf * s);   // RED, no-return, spread addresses
    }
}

// ---------------- launch ----------------
extern "C" void kernel_launch(void* const* d_in, const int* in_sizes, int n_in,
                              void* d_out, int out_size)
{
    const float* x      = (const float*)d_in[0];
    const float* cp     = (const float*)d_in[1];
    const float* n_prev = (const float*)d_in[2];
    const float* Wq     = (const float*)d_in[3];
    const float* bq     = (const float*)d_in[4];
    const float* Wk     = (const float*)d_in[5];
    const float* bk     = (const float*)d_in[6];
    const float* Wv     = (const float*)d_in[7];
    const float* bV     = (const float*)d_in[8];
    const float* Wi     = (const float*)d_in[9];
    const float* bi     = (const float*)d_in[10];
    const float* Wf     = (const float*)d_in[11];
    const float* bf     = (const float*)d_in[12];
    const float* Wo     = (const float*)d_in[13];
    const float* bo     = (const float*)d_in[14];

    float* out  = (float*)d_out;
    float* outH = out;                        // ht: M
    float* outC = out + MM;                   // C : M*M
    float* outN = out + MM + (size_t)MM * MM; // n : M

    mv_kernel<<<MM + 1, 256>>>(x, Wq, bq, Wk, bk, Wv, bV,
                               Wi, bi, Wf, bf, Wo, bo);
    nred2_kernel<<<1, 1024>>>(n_prev, outN, outH);
    cp_partial<<<4096, 256>>>(cp, outC, outH);
}